// round 1
// baseline (speedup 1.0000x reference)
#include <cuda_runtime.h>

// ---------------- problem constants ----------------
#define NB 512
constexpr int NA  = 32;     // atoms per molecule
constexpr int D   = 128;    // feature dim
constexpr int R   = 50;     // n_rbf
constexpr int RP  = 52;     // padded rbf (float4-aligned rows, zero pad)
constexpr int NL  = 6;      // interaction layers
constexpr int NP  = 496;    // unordered pairs (32*31/2)
constexpr int CH  = 62;     // pairs per chunk
constexpr int NCH = 8;      // 8 * 62 = 496
constexpr float CUTOFF = 5.0f;
constexpr float WIDTH  = CUTOFF / (R - 1);
constexpr float COEFF  = -0.5f / (WIDTH * WIDTH);
constexpr float LN2    = 0.69314718055994531f;
constexpr float PIF    = 3.14159265358979323846f;

// ---------------- smem layout (float offsets) ----------------
constexpr int OFF_WF1  = 0;               // 52*128   = 6656 (rows 50,51 zeroed)
constexpr int OFF_WF2  = 6656;            // 128*128  = 16384
constexpr int OFF_X    = 23040;           // 32*128   = 4096
constexpr int OFF_XF   = 27136;           // 4096
constexpr int OFF_AGG  = 31232;           // 4096  (reused as mol[] in head)
constexpr int OFF_H1   = 35328;           // 62*128   = 7936 (reused as t1 / head h)
constexpr int OFF_WC   = 43264;           // 62*128   = 7936
constexpr int OFF_F    = 51200;           // 62*52    = 3224 (cols 50,51 zeroed)
constexpr int OFF_DIST = 54424;           // 496
constexpr int OFF_RCUT = 54920;           // 496
constexpr int OFF_BF1  = 55416;           // 128
constexpr int OFF_BF2  = 55544;           // 128
constexpr int OFF_BO1  = 55672;           // 128
constexpr int OFF_BO2  = 55800;           // 128
constexpr int OFF_POS  = 55928;           // 96
constexpr int OFF_PAIR = 56024;           // 248 floats = 496 ushort
constexpr int SMEM_FLOATS = 56272;        // 225088 bytes

// shifted softplus: softplus(x) - ln2, numerically stable
__device__ __forceinline__ float sspf(float x) {
    return fmaxf(x, 0.f) + log1pf(__expf(-fabsf(x))) - LN2;
}

__device__ __forceinline__ void fma4(float4& acc, float a, const float4& b) {
    acc.x = fmaf(a, b.x, acc.x);
    acc.y = fmaf(a, b.y, acc.y);
    acc.z = fmaf(a, b.z, acc.z);
    acc.w = fmaf(a, b.w, acc.w);
}
__device__ __forceinline__ void fma4v(float4& acc, const float4& a, const float4& b) {
    acc.x = fmaf(a.x, b.x, acc.x);
    acc.y = fmaf(a.y, b.y, acc.y);
    acc.z = fmaf(a.z, b.z, acc.z);
    acc.w = fmaf(a.w, b.w, acc.w);
}
__device__ __forceinline__ float comp(const float4& v, int k) {
    return ((const float*)&v)[k];
}

__global__ void __launch_bounds__(NB, 1) schnet_kernel(
    const int*   __restrict__ Z,
    const float* __restrict__ pos,
    const float* __restrict__ emb,
    const float* __restrict__ Wi,
    const float* __restrict__ Wf1, const float* __restrict__ bf1,
    const float* __restrict__ Wf2, const float* __restrict__ bf2,
    const float* __restrict__ Wo1, const float* __restrict__ bo1,
    const float* __restrict__ Wo2, const float* __restrict__ bo2,
    const float* __restrict__ Wh1, const float* __restrict__ bh1,
    const float* __restrict__ Wh2, const float* __restrict__ bh2,
    float* __restrict__ out)
{
    extern __shared__ float sm[];
    unsigned short* pairsS = (unsigned short*)(sm + OFF_PAIR);

    const int tid  = threadIdx.x;
    const int lane = tid & 31;
    const int w    = tid >> 5;        // 16 warps
    const int mol  = blockIdx.x;
    const int c4   = lane << 2;       // this lane's 4 output channels

    // ---------- init: positions, pair table, embedding ----------
    if (tid < NA * 3) sm[OFF_POS + tid] = pos[mol * NA * 3 + tid];
    if (tid < NP) {
        int p = tid, i = 0, base = 0;
        while (p >= base + (31 - i)) { base += 31 - i; i++; }
        int j = i + 1 + (p - base);
        pairsS[tid] = (unsigned short)((i << 5) | j);
    }
    for (int idx = tid; idx < NA * D; idx += NB) {
        int a = idx >> 7, c = idx & (D - 1);
        sm[OFF_X + idx] = emb[Z[mol * NA + a] * D + c];
    }
    __syncthreads();
    if (tid < NP) {
        int pr = pairsS[tid]; int i = pr >> 5, j = pr & 31;
        float dx = sm[OFF_POS + i * 3 + 0] - sm[OFF_POS + j * 3 + 0];
        float dy = sm[OFF_POS + i * 3 + 1] - sm[OFF_POS + j * 3 + 1];
        float dz = sm[OFF_POS + i * 3 + 2] - sm[OFF_POS + j * 3 + 2];
        float d  = sqrtf(dx * dx + dy * dy + dz * dz);
        sm[OFF_DIST + tid] = d;
        sm[OFF_RCUT + tid] = (d < CUTOFF) ? 0.5f * (__cosf(d * (PIF / CUTOFF)) + 1.f) : 0.f;
    }
    __syncthreads();

    // ---------- interaction layers ----------
    for (int l = 0; l < NL; l++) {
        // stage layer filter weights in smem (L2-hot across CTAs)
        {
            const float4* s1 = (const float4*)(Wf1 + l * R * D);
            for (int idx = tid; idx < RP * D / 4; idx += NB) {
                float4 v = (idx < R * D / 4) ? s1[idx] : make_float4(0.f, 0.f, 0.f, 0.f);
                ((float4*)(sm + OFF_WF1))[idx] = v;
            }
            const float4* s2 = (const float4*)(Wf2 + l * D * D);
            for (int idx = tid; idx < D * D / 4; idx += NB)
                ((float4*)(sm + OFF_WF2))[idx] = s2[idx];
            if (tid < D) {
                sm[OFF_BF1 + tid] = bf1[l * D + tid];
                sm[OFF_BF2 + tid] = bf2[l * D + tid];
                sm[OFF_BO1 + tid] = bo1[l * D + tid];
                sm[OFF_BO2 + tid] = bo2[l * D + tid];
            }
        }
        // in2f: xf = x @ Wi[l]  (no bias). 16 warps x 2 rows.
        {
            const float* wi = Wi + l * D * D;
            const int r0 = w * 2;
            float4 acc0 = {0, 0, 0, 0}, acc1 = {0, 0, 0, 0};
            #pragma unroll 4
            for (int k = 0; k < D; k += 4) {
                float4 a0 = *(const float4*)(sm + OFF_X + r0 * D + k);
                float4 a1 = *(const float4*)(sm + OFF_X + (r0 + 1) * D + k);
                #pragma unroll
                for (int kk = 0; kk < 4; kk++) {
                    float4 b = *(const float4*)(wi + (k + kk) * D + c4);
                    fma4(acc0, comp(a0, kk), b);
                    fma4(acc1, comp(a1, kk), b);
                }
            }
            *(float4*)(sm + OFF_XF + r0 * D + c4)       = acc0;
            *(float4*)(sm + OFF_XF + (r0 + 1) * D + c4) = acc1;
        }
        float4 accB0 = {0, 0, 0, 0}, accB1 = {0, 0, 0, 0};  // message acc: rows w, w+16
        __syncthreads();  // xf, Wf1s, Wf2s, biases ready

        for (int c = 0; c < NCH; c++) {
            // RBF expansion for this chunk (recomputed per layer; cheap MUFU)
            for (int idx = tid; idx < CH * RP; idx += NB) {
                int p = idx / RP, r = idx - p * RP;
                float v = 0.f;
                if (r < R) {
                    float d = sm[OFF_DIST + c * CH + p];
                    float t = d - (float)r * WIDTH;
                    v = __expf(COEFF * t * t);
                }
                sm[OFF_F + idx] = v;
            }
            __syncthreads();
            // GEMM1: H1[62][128] = ssp(F @ Wf1 + bf1). 16 warps x 4 rows.
            {
                const int r0 = w * 4;
                int rA0 = min(r0 + 0, CH - 1), rA1 = min(r0 + 1, CH - 1);
                int rA2 = min(r0 + 2, CH - 1), rA3 = min(r0 + 3, CH - 1);
                float4 ac0 = {0,0,0,0}, ac1 = {0,0,0,0}, ac2 = {0,0,0,0}, ac3 = {0,0,0,0};
                #pragma unroll 2
                for (int k = 0; k < RP; k += 4) {
                    float4 a0 = *(const float4*)(sm + OFF_F + rA0 * RP + k);
                    float4 a1 = *(const float4*)(sm + OFF_F + rA1 * RP + k);
                    float4 a2 = *(const float4*)(sm + OFF_F + rA2 * RP + k);
                    float4 a3 = *(const float4*)(sm + OFF_F + rA3 * RP + k);
                    #pragma unroll
                    for (int kk = 0; kk < 4; kk++) {
                        float4 b = *(const float4*)(sm + OFF_WF1 + (k + kk) * D + c4);
                        fma4(ac0, comp(a0, kk), b);
                        fma4(ac1, comp(a1, kk), b);
                        fma4(ac2, comp(a2, kk), b);
                        fma4(ac3, comp(a3, kk), b);
                    }
                }
                float4 bb = *(const float4*)(sm + OFF_BF1 + c4);
                float4* accs[4] = {&ac0, &ac1, &ac2, &ac3};
                #pragma unroll
                for (int m = 0; m < 4; m++) {
                    int row = r0 + m;
                    if (row < CH) {
                        float4 o;
                        o.x = sspf(accs[m]->x + bb.x);
                        o.y = sspf(accs[m]->y + bb.y);
                        o.z = sspf(accs[m]->z + bb.z);
                        o.w = sspf(accs[m]->w + bb.w);
                        *(float4*)(sm + OFF_H1 + row * D + c4) = o;
                    }
                }
            }
            __syncthreads();
            // GEMM2: Wc[62][128] = (H1 @ Wf2 + bf2) * rcut
            {
                const int r0 = w * 4;
                int rA0 = min(r0 + 0, CH - 1), rA1 = min(r0 + 1, CH - 1);
                int rA2 = min(r0 + 2, CH - 1), rA3 = min(r0 + 3, CH - 1);
                float4 ac0 = {0,0,0,0}, ac1 = {0,0,0,0}, ac2 = {0,0,0,0}, ac3 = {0,0,0,0};
                #pragma unroll 2
                for (int k = 0; k < D; k += 4) {
                    float4 a0 = *(const float4*)(sm + OFF_H1 + rA0 * D + k);
                    float4 a1 = *(const float4*)(sm + OFF_H1 + rA1 * D + k);
                    float4 a2 = *(const float4*)(sm + OFF_H1 + rA2 * D + k);
                    float4 a3 = *(const float4*)(sm + OFF_H1 + rA3 * D + k);
                    #pragma unroll
                    for (int kk = 0; kk < 4; kk++) {
                        float4 b = *(const float4*)(sm + OFF_WF2 + (k + kk) * D + c4);
                        fma4(ac0, comp(a0, kk), b);
                        fma4(ac1, comp(a1, kk), b);
                        fma4(ac2, comp(a2, kk), b);
                        fma4(ac3, comp(a3, kk), b);
                    }
                }
                float4 bb = *(const float4*)(sm + OFF_BF2 + c4);
                float4* accs[4] = {&ac0, &ac1, &ac2, &ac3};
                #pragma unroll
                for (int m = 0; m < 4; m++) {
                    int row = r0 + m;
                    if (row < CH) {
                        float rc = sm[OFF_RCUT + c * CH + row];
                        float4 o;
                        o.x = (accs[m]->x + bb.x) * rc;
                        o.y = (accs[m]->y + bb.y) * rc;
                        o.z = (accs[m]->z + bb.z) * rc;
                        o.w = (accs[m]->w + bb.w) * rc;
                        *(float4*)(sm + OFF_WC + row * D + c4) = o;
                    }
                }
            }
            __syncthreads();
            // message accumulate (symmetric W): warp w owns rows w and w+16
            {
                const int base = c * CH;
                const int w1 = w + 16;
                for (int p = 0; p < CH; p++) {
                    int pr = pairsS[base + p];
                    int i = pr >> 5, j = pr & 31;
                    int o0 = (i == w)  ? j : ((j == w)  ? i : -1);
                    int o1 = (i == w1) ? j : ((j == w1) ? i : -1);
                    if (o0 >= 0) {
                        float4 wv = *(const float4*)(sm + OFF_WC + p * D + c4);
                        float4 xv = *(const float4*)(sm + OFF_XF + o0 * D + c4);
                        fma4v(accB0, wv, xv);
                    }
                    if (o1 >= 0) {
                        float4 wv = *(const float4*)(sm + OFF_WC + p * D + c4);
                        float4 xv = *(const float4*)(sm + OFF_XF + o1 * D + c4);
                        fma4v(accB1, wv, xv);
                    }
                }
            }
            // no barrier needed: next chunk's RBF write targets OFF_F only and is
            // followed by a barrier before any warp touches H1/Wc again.
        }
        // dump message accumulators to smem agg
        *(float4*)(sm + OFF_AGG + w * D + c4)        = accB0;
        *(float4*)(sm + OFF_AGG + (w + 16) * D + c4) = accB1;
        __syncthreads();
        // f2out part 1: t1 = ssp(agg @ Wo1 + bo1)   (t1 reuses H1 region)
        {
            const float* wo1 = Wo1 + l * D * D;
            const int r0 = w * 2;
            float4 acc0 = {0, 0, 0, 0}, acc1 = {0, 0, 0, 0};
            #pragma unroll 4
            for (int k = 0; k < D; k += 4) {
                float4 a0 = *(const float4*)(sm + OFF_AGG + r0 * D + k);
                float4 a1 = *(const float4*)(sm + OFF_AGG + (r0 + 1) * D + k);
                #pragma unroll
                for (int kk = 0; kk < 4; kk++) {
                    float4 b = *(const float4*)(wo1 + (k + kk) * D + c4);
                    fma4(acc0, comp(a0, kk), b);
                    fma4(acc1, comp(a1, kk), b);
                }
            }
            float4 bb = *(const float4*)(sm + OFF_BO1 + c4);
            float4 o0, o1;
            o0.x = sspf(acc0.x + bb.x); o0.y = sspf(acc0.y + bb.y);
            o0.z = sspf(acc0.z + bb.z); o0.w = sspf(acc0.w + bb.w);
            o1.x = sspf(acc1.x + bb.x); o1.y = sspf(acc1.y + bb.y);
            o1.z = sspf(acc1.z + bb.z); o1.w = sspf(acc1.w + bb.w);
            *(float4*)(sm + OFF_H1 + r0 * D + c4)       = o0;
            *(float4*)(sm + OFF_H1 + (r0 + 1) * D + c4) = o1;
        }
        __syncthreads();
        // f2out part 2 + residual: x += t1 @ Wo2 + bo2
        {
            const float* wo2 = Wo2 + l * D * D;
            const int r0 = w * 2;
            float4 acc0 = {0, 0, 0, 0}, acc1 = {0, 0, 0, 0};
            #pragma unroll 4
            for (int k = 0; k < D; k += 4) {
                float4 a0 = *(const float4*)(sm + OFF_H1 + r0 * D + k);
                float4 a1 = *(const float4*)(sm + OFF_H1 + (r0 + 1) * D + k);
                #pragma unroll
                for (int kk = 0; kk < 4; kk++) {
                    float4 b = *(const float4*)(wo2 + (k + kk) * D + c4);
                    fma4(acc0, comp(a0, kk), b);
                    fma4(acc1, comp(a1, kk), b);
                }
            }
            float4 bb = *(const float4*)(sm + OFF_BO2 + c4);
            float4 x0 = *(const float4*)(sm + OFF_X + r0 * D + c4);
            float4 x1 = *(const float4*)(sm + OFF_X + (r0 + 1) * D + c4);
            x0.x += acc0.x + bb.x; x0.y += acc0.y + bb.y;
            x0.z += acc0.z + bb.z; x0.w += acc0.w + bb.w;
            x1.x += acc1.x + bb.x; x1.y += acc1.y + bb.y;
            x1.z += acc1.z + bb.z; x1.w += acc1.w + bb.w;
            *(float4*)(sm + OFF_X + r0 * D + c4)       = x0;
            *(float4*)(sm + OFF_X + (r0 + 1) * D + c4) = x1;
        }
        __syncthreads();
    }

    // ---------- readout head ----------
    if (tid < D) {
        float s = 0.f;
        #pragma unroll
        for (int i = 0; i < NA; i++) s += sm[OFF_X + i * D + tid];
        sm[OFF_AGG + tid] = s;              // mol[]
    }
    __syncthreads();
    if (tid < D) {
        float acc = 0.f;
        #pragma unroll 8
        for (int k = 0; k < D; k++) acc = fmaf(sm[OFF_AGG + k], Wh1[k * D + tid], acc);
        float hpre = acc + bh1[tid];
        float h = hpre / (1.f + __expf(-hpre));   // silu
        sm[OFF_H1 + tid] = h * Wh2[tid];
    }
    __syncthreads();
    if (tid == 0) {
        float s = bh2[0];
        #pragma unroll 8
        for (int k = 0; k < D; k++) s += sm[OFF_H1 + k];
        out[mol] = s;
    }
}

extern "C" void kernel_launch(void* const* d_in, const int* in_sizes, int n_in,
                              void* d_out, int out_size)
{
    const int*   Z   = (const int*)  d_in[0];
    const float* pos = (const float*)d_in[1];
    // d_in[2..5] = idx_i, idx_j, batch_idx, n_atoms: structure is implied
    // (complete intra-molecule graph, 32 contiguous atoms/molecule) - unused.
    const float* emb = (const float*)d_in[6];
    const float* Wi  = (const float*)d_in[7];
    const float* Wf1 = (const float*)d_in[8];
    const float* bf1 = (const float*)d_in[9];
    const float* Wf2 = (const float*)d_in[10];
    const float* bf2 = (const float*)d_in[11];
    const float* Wo1 = (const float*)d_in[12];
    const float* bo1 = (const float*)d_in[13];
    const float* Wo2 = (const float*)d_in[14];
    const float* bo2 = (const float*)d_in[15];
    const float* Wh1 = (const float*)d_in[16];
    const float* bh1 = (const float*)d_in[17];
    const float* Wh2 = (const float*)d_in[18];
    const float* bh2 = (const float*)d_in[19];

    const int B = out_size;                       // molecules
    const size_t smem = SMEM_FLOATS * sizeof(float);
    cudaFuncSetAttribute(schnet_kernel,
                         cudaFuncAttributeMaxDynamicSharedMemorySize, (int)smem);
    schnet_kernel<<<B, NB, smem>>>(Z, pos, emb, Wi, Wf1, bf1, Wf2, bf2,
                                   Wo1, bo1, Wo2, bo2, Wh1, bh1, Wh2, bh2,
                                   (float*)d_out);
}

// round 3
// speedup vs baseline: 1.5596x; 1.5596x over previous
#include <cuda_runtime.h>
#include <cuda_bf16.h>
#include <cstdint>

#define NB 512
constexpr int NA = 32;      // atoms / molecule
constexpr int DD = 128;     // feature dim
constexpr int RR = 50;      // n_rbf
constexpr int NP = 496;     // unordered pairs
constexpr int NLAY = 6;
constexpr int NT = 4;       // M-tiles of 128 pair-rows (512 padded)
constexpr float CUTOFF = 5.0f;
constexpr float WIDTH  = CUTOFF / (RR - 1);
constexpr float COEFF  = -0.5f / (WIDTH * WIDTH);
constexpr float LN2    = 0.69314718055994531f;
constexpr float PIF    = 3.14159265358979323846f;

constexpr int STRA1 = 144;   // A1 row stride bytes (72 bf16; 64 k used)
constexpr int STRB  = 272;   // B1/B2/H1 row stride bytes (136 bf16; 128 used)
constexpr int WSTR  = 132;   // Ws row stride (floats)

// ---------------- smem byte offsets ----------------
constexpr int SB_B1H = 0;            // 64 x 136 bf16 = 17408
constexpr int SB_B1L = 17408;
constexpr int SB_B2H = 34816;        // 128 x 136 bf16 = 34816
constexpr int SB_B2L = 69632;
constexpr int SB_UNI = 104448;       // 69632-byte union region:
constexpr int UNI_A1H = SB_UNI;          //  A1 hi 128x72 bf16 = 18432
constexpr int UNI_A1L = SB_UNI + 18432;  //  A1 lo
constexpr int UNI_H1H = SB_UNI;          //  H1 hi 128x136 bf16 = 34816
constexpr int UNI_H1L = SB_UNI + 34816;  //  H1 lo
                                         //  Ws 128x132 f32 = 67584
                                         //  AGG 32x128 f32 @ +0 ; T1 @ +16384
constexpr int SB_X    = 174080;      // 32x128 f32
constexpr int SB_XF   = 190464;      // 32x128 f32
constexpr int SB_DIST = 206848;      // 512 f32
constexpr int SB_RCUT = 208896;      // 512 f32
constexpr int SB_BF1  = 210944;      // 128 f32 each
constexpr int SB_BF2  = 211456;
constexpr int SB_BO1  = 211968;
constexpr int SB_BO2  = 212480;
constexpr int SB_POS  = 212992;      // 96 f32
constexpr int SB_PAIR = 213504;      // 512 u16
constexpr int SMEM_BYTES = 214528;

// ---------------- low-level helpers ----------------
__device__ __forceinline__ uint32_t smem_u32(const void* p) {
    uint32_t a;
    asm("{ .reg .u64 t; cvta.to.shared.u64 t, %1; cvt.u32.u64 %0, t; }"
        : "=r"(a) : "l"(p));
    return a;
}
__device__ __forceinline__ void ldsm4(uint32_t* r, uint32_t a) {
    asm volatile("ldmatrix.sync.aligned.m8n8.x4.shared.b16 {%0,%1,%2,%3}, [%4];"
        : "=r"(r[0]), "=r"(r[1]), "=r"(r[2]), "=r"(r[3]) : "r"(a));
}
__device__ __forceinline__ void ldsm4t(uint32_t* r, uint32_t a) {
    asm volatile("ldmatrix.sync.aligned.m8n8.x4.trans.shared.b16 {%0,%1,%2,%3}, [%4];"
        : "=r"(r[0]), "=r"(r[1]), "=r"(r[2]), "=r"(r[3]) : "r"(a));
}
__device__ __forceinline__ void mmabf(float* c, const uint32_t* a, const uint32_t* b) {
    asm volatile("mma.sync.aligned.m16n8k16.row.col.f32.bf16.bf16.f32 "
        "{%0,%1,%2,%3}, {%4,%5,%6,%7}, {%8,%9}, {%0,%1,%2,%3};"
        : "+f"(c[0]), "+f"(c[1]), "+f"(c[2]), "+f"(c[3])
        : "r"(a[0]), "r"(a[1]), "r"(a[2]), "r"(a[3]), "r"(b[0]), "r"(b[1]));
}
__device__ __forceinline__ void split2(float x, uint32_t& h, uint32_t& l) {
    __nv_bfloat16 hb = __float2bfloat16(x);
    __nv_bfloat16 lb = __float2bfloat16(x - __bfloat162float(hb));
    h = (uint32_t)__bfloat16_as_ushort(hb);
    l = (uint32_t)__bfloat16_as_ushort(lb);
}
__device__ __forceinline__ float sspf(float x) {   // softplus(x) - ln2
    float r = __logf(fmaf(0.5f, __expf(x), 0.5f));
    return (x > 20.f) ? x - LN2 : r;
}
__device__ __forceinline__ void fma4(float4& a, float s, const float4& b) {
    a.x = fmaf(s, b.x, a.x); a.y = fmaf(s, b.y, a.y);
    a.z = fmaf(s, b.z, a.z); a.w = fmaf(s, b.w, a.w);
}
__device__ __forceinline__ void fma4v(float4& a, const float4& s, const float4& b) {
    a.x = fmaf(s.x, b.x, a.x); a.y = fmaf(s.y, b.y, a.y);
    a.z = fmaf(s.z, b.z, a.z); a.w = fmaf(s.w, b.w, a.w);
}
__device__ __forceinline__ float comp(const float4& v, int k) { return ((const float*)&v)[k]; }

// split-bf16 3-pass GEMM tile: warp computes C[32x32] at (mr, nc).
// A stored [m][k] row-major (stride SA bytes), B stored [k][n] (stride STRB).
template<int KS, int SA>
__device__ __forceinline__ void gemm_split(
    uint32_t aH, uint32_t aL, uint32_t bH, uint32_t bL,
    int mr, int nc, int lane, float (*c)[4])
{
    const uint32_t aoff = (uint32_t)((mr + (lane & 7) + ((lane >> 3) & 1) * 8) * SA
                                     + ((lane >> 4) & 1) * 16);
    const uint32_t boff = (uint32_t)(((lane & 7) + ((lane >> 3) & 1) * 8) * STRB
                                     + (nc + ((lane >> 4) & 1) * 8) * 2);
    #pragma unroll
    for (int ks = 0; ks < KS; ks++) {
        const uint32_t ao = aoff + ks * 32;
        const uint32_t bo = boff + ks * 16 * STRB;
        uint32_t Ah[8], Bh[8], Bx[8];
        ldsm4(Ah, aH + ao); ldsm4(Ah + 4, aH + ao + 16 * SA);
        ldsm4t(Bh, bH + bo); ldsm4t(Bh + 4, bH + bo + 32);
        #pragma unroll
        for (int mi = 0; mi < 2; mi++)
            #pragma unroll
            for (int ni = 0; ni < 4; ni++)
                mmabf(c[mi * 4 + ni], Ah + mi * 4, Bh + ni * 2);
        ldsm4t(Bx, bL + bo); ldsm4t(Bx + 4, bL + bo + 32);      // B lo
        #pragma unroll
        for (int mi = 0; mi < 2; mi++)
            #pragma unroll
            for (int ni = 0; ni < 4; ni++)
                mmabf(c[mi * 4 + ni], Ah + mi * 4, Bx + ni * 2);
        ldsm4(Bx, aL + ao); ldsm4(Bx + 4, aL + ao + 16 * SA);   // A lo
        #pragma unroll
        for (int mi = 0; mi < 2; mi++)
            #pragma unroll
            for (int ni = 0; ni < 4; ni++)
                mmabf(c[mi * 4 + ni], Bx + mi * 4, Bh + ni * 2);
    }
}

__global__ void __launch_bounds__(NB, 1)
schnet_hmma(const int*   __restrict__ Z,   const float* __restrict__ pos,
            const float* __restrict__ emb, const float* __restrict__ Wi,
            const float* __restrict__ Wf1, const float* __restrict__ bf1,
            const float* __restrict__ Wf2, const float* __restrict__ bf2,
            const float* __restrict__ Wo1, const float* __restrict__ bo1,
            const float* __restrict__ Wo2, const float* __restrict__ bo2,
            const float* __restrict__ Wh1, const float* __restrict__ bh1,
            const float* __restrict__ Wh2, const float* __restrict__ bh2,
            float* __restrict__ out)
{
    extern __shared__ __align__(1024) char smc[];
    float* Xs    = (float*)(smc + SB_X);
    float* XFs   = (float*)(smc + SB_XF);
    float* DISTs = (float*)(smc + SB_DIST);
    float* RCUTs = (float*)(smc + SB_RCUT);
    float* BF1s  = (float*)(smc + SB_BF1);
    float* BF2s  = (float*)(smc + SB_BF2);
    float* BO1s  = (float*)(smc + SB_BO1);
    float* BO2s  = (float*)(smc + SB_BO2);
    float* POSs  = (float*)(smc + SB_POS);
    float* Wsf   = (float*)(smc + SB_UNI);            // 128 x WSTR f32
    float* AGGf  = (float*)(smc + SB_UNI);            // 32 x 128 f32
    float* T1f   = (float*)(smc + SB_UNI + 16384);    // 32 x 128 f32
    unsigned short* PAIRs = (unsigned short*)(smc + SB_PAIR);
    const uint32_t smb = smem_u32(smc);

    const int tid = threadIdx.x, lane = tid & 31, w = tid >> 5;
    const int wr = w & 3, wc = w >> 2;     // warp tile coords in 128x128
    const int mol = blockIdx.x;
    const int c4 = lane << 2;

    // ---------- init ----------
    if (tid < NA * 3) POSs[tid] = pos[mol * NA * 3 + tid];
    {
        int p = tid;
        unsigned short pr = 0;
        if (p < NP) {
            int i = 0, base = 0;
            while (p >= base + (31 - i)) { base += 31 - i; i++; }
            int j = i + 1 + (p - base);
            pr = (unsigned short)((i << 5) | j);
        }
        PAIRs[tid] = pr;
    }
    for (int idx = tid; idx < NA * DD; idx += NB) {
        int a = idx >> 7, cc = idx & (DD - 1);
        Xs[idx] = emb[Z[mol * NA + a] * DD + cc];
    }
    __syncthreads();
    {
        float d = 4.0f * CUTOFF;   // pad rows -> F underflows to 0, rcut 0
        float rc = 0.f;
        if (tid < NP) {
            int pr = PAIRs[tid]; int i = pr >> 5, j = pr & 31;
            float dx = POSs[i*3+0] - POSs[j*3+0];
            float dy = POSs[i*3+1] - POSs[j*3+1];
            float dz = POSs[i*3+2] - POSs[j*3+2];
            d = sqrtf(dx*dx + dy*dy + dz*dz);
            rc = (d < CUTOFF) ? 0.5f * (__cosf(d * (PIF / CUTOFF)) + 1.f) : 0.f;
        }
        DISTs[tid] = d; RCUTs[tid] = rc;
    }

    // ---------- interaction layers ----------
    for (int l = 0; l < NLAY; l++) {
        // stage B1 = Wf1[l] (k x n, pad k to 64), B2 = Wf2[l], split hi/lo
        {
            const float* wf1g = Wf1 + l * RR * DD;
            for (int idx = tid; idx < 64 * DD; idx += NB) {
                int k = idx >> 7, n = idx & 127;
                float v = (k < RR) ? wf1g[k * DD + n] : 0.f;
                uint32_t h, lo; split2(v, h, lo);
                *(uint16_t*)(smc + SB_B1H + k * STRB + n * 2) = (uint16_t)h;
                *(uint16_t*)(smc + SB_B1L + k * STRB + n * 2) = (uint16_t)lo;
            }
            const float* wf2g = Wf2 + l * DD * DD;
            for (int idx = tid; idx < DD * DD; idx += NB) {
                int k = idx >> 7, n = idx & 127;
                float v = wf2g[k * DD + n];
                uint32_t h, lo; split2(v, h, lo);
                *(uint16_t*)(smc + SB_B2H + k * STRB + n * 2) = (uint16_t)h;
                *(uint16_t*)(smc + SB_B2L + k * STRB + n * 2) = (uint16_t)lo;
            }
            if (tid < DD) {
                BF1s[tid] = bf1[l * DD + tid];
                BF2s[tid] = bf2[l * DD + tid];
                BO1s[tid] = bo1[l * DD + tid];
                BO2s[tid] = bo2[l * DD + tid];
            }
        }
        // in2f: xf = x @ Wi[l]  (fp32 SIMT, 16 warps x 2 rows)
        {
            const float* wi = Wi + l * DD * DD;
            const int r0 = w * 2;
            float4 acc0 = {0,0,0,0}, acc1 = {0,0,0,0};
            #pragma unroll 4
            for (int k = 0; k < DD; k += 4) {
                float4 a0 = *(const float4*)(Xs + r0 * DD + k);
                float4 a1 = *(const float4*)(Xs + (r0 + 1) * DD + k);
                #pragma unroll
                for (int kk = 0; kk < 4; kk++) {
                    float4 b = *(const float4*)(wi + (k + kk) * DD + c4);
                    fma4(acc0, comp(a0, kk), b);
                    fma4(acc1, comp(a1, kk), b);
                }
            }
            *(float4*)(XFs + r0 * DD + c4)       = acc0;
            *(float4*)(XFs + (r0 + 1) * DD + c4) = acc1;
        }
        __syncthreads();

        float4 accB0 = {0,0,0,0}, accB1 = {0,0,0,0};   // msg rows w, w+16

        for (int t = 0; t < NT; t++) {
            // ---- fill A1 = F tile (RBF), split hi/lo ----
            for (int idx = tid; idx < 128 * 32; idx += NB) {
                int row = idx >> 5, kp = idx & 31;
                float d = DISTs[t * 128 + row];
                int k0 = kp * 2;
                float t0 = d - (float)k0 * WIDTH;
                float t1 = d - (float)(k0 + 1) * WIDTH;
                float f0 = (k0     < RR) ? __expf(COEFF * t0 * t0) : 0.f;
                float f1 = (k0 + 1 < RR) ? __expf(COEFF * t1 * t1) : 0.f;
                uint32_t h0, l0, h1, l1;
                split2(f0, h0, l0); split2(f1, h1, l1);
                *(uint32_t*)(smc + UNI_A1H + row * STRA1 + kp * 4) = h0 | (h1 << 16);
                *(uint32_t*)(smc + UNI_A1L + row * STRA1 + kp * 4) = l0 | (l1 << 16);
            }
            __syncthreads();
            // ---- GEMM1: C = F @ Wf1 ----
            float c[8][4];
            #pragma unroll
            for (int a = 0; a < 8; a++)
                { c[a][0]=0.f; c[a][1]=0.f; c[a][2]=0.f; c[a][3]=0.f; }
            gemm_split<4, STRA1>(smb + UNI_A1H, smb + UNI_A1L,
                                 smb + SB_B1H, smb + SB_B1L,
                                 wr * 32, wc * 32, lane, c);
            __syncthreads();   // A1 dead before H1 overwrite
            // ---- epilogue1: ssp(C + bf1) -> split -> H1 ----
            #pragma unroll
            for (int mi = 0; mi < 2; mi++)
                #pragma unroll
                for (int ni = 0; ni < 4; ni++)
                    #pragma unroll
                    for (int h = 0; h < 2; h++) {
                        int row = wr * 32 + mi * 16 + (lane >> 2) + h * 8;
                        int col = wc * 32 + ni * 8 + (lane & 3) * 2;
                        float v0 = sspf(c[mi*4+ni][h*2+0] + BF1s[col]);
                        float v1 = sspf(c[mi*4+ni][h*2+1] + BF1s[col+1]);
                        uint32_t h0, l0, h1, l1;
                        split2(v0, h0, l0); split2(v1, h1, l1);
                        *(uint32_t*)(smc + UNI_H1H + row * STRB + col * 2) = h0 | (h1 << 16);
                        *(uint32_t*)(smc + UNI_H1L + row * STRB + col * 2) = l0 | (l1 << 16);
                    }
            __syncthreads();
            // ---- GEMM2: C = H1 @ Wf2 ----
            #pragma unroll
            for (int a = 0; a < 8; a++)
                { c[a][0]=0.f; c[a][1]=0.f; c[a][2]=0.f; c[a][3]=0.f; }
            gemm_split<8, STRB>(smb + UNI_H1H, smb + UNI_H1L,
                                smb + SB_B2H, smb + SB_B2L,
                                wr * 32, wc * 32, lane, c);
            __syncthreads();   // H1 dead before Ws overwrite
            // ---- epilogue2: (C + bf2) * rcut -> Ws ----
            #pragma unroll
            for (int mi = 0; mi < 2; mi++)
                #pragma unroll
                for (int ni = 0; ni < 4; ni++)
                    #pragma unroll
                    for (int h = 0; h < 2; h++) {
                        int row = wr * 32 + mi * 16 + (lane >> 2) + h * 8;
                        int col = wc * 32 + ni * 8 + (lane & 3) * 2;
                        float rc = RCUTs[t * 128 + row];
                        float2 v;
                        v.x = (c[mi*4+ni][h*2+0] + BF2s[col])   * rc;
                        v.y = (c[mi*4+ni][h*2+1] + BF2s[col+1]) * rc;
                        *(float2*)(Wsf + row * WSTR + col) = v;
                    }
            __syncthreads();
            // ---- message accumulate (symmetric pairs) ----
            {
                const int pv = min(128, NP - t * 128);
                const int w1 = w + 16;
                for (int p = 0; p < pv; p++) {
                    int pr = PAIRs[t * 128 + p];
                    int i = pr >> 5, j = pr & 31;
                    int o0 = (i == w)  ? j : ((j == w)  ? i : -1);
                    int o1 = (i == w1) ? j : ((j == w1) ? i : -1);
                    if (o0 >= 0) {
                        float4 wv = *(const float4*)(Wsf + p * WSTR + c4);
                        float4 xv = *(const float4*)(XFs + o0 * DD + c4);
                        fma4v(accB0, wv, xv);
                    }
                    if (o1 >= 0) {
                        float4 wv = *(const float4*)(Wsf + p * WSTR + c4);
                        float4 xv = *(const float4*)(XFs + o1 * DD + c4);
                        fma4v(accB1, wv, xv);
                    }
                }
            }
            __syncthreads();   // Ws dead before next tile's A1 fill
        }
        // dump message accumulators to AGG (union region, Ws dead)
        *(float4*)(AGGf + w * DD + c4)        = accB0;
        *(float4*)(AGGf + (w + 16) * DD + c4) = accB1;
        __syncthreads();
        // f2out p1: t1 = ssp(agg @ Wo1 + bo1)
        {
            const float* wo1 = Wo1 + l * DD * DD;
            const int r0 = w * 2;
            float4 acc0 = {0,0,0,0}, acc1 = {0,0,0,0};
            #pragma unroll 4
            for (int k = 0; k < DD; k += 4) {
                float4 a0 = *(const float4*)(AGGf + r0 * DD + k);
                float4 a1 = *(const float4*)(AGGf + (r0 + 1) * DD + k);
                #pragma unroll
                for (int kk = 0; kk < 4; kk++) {
                    float4 b = *(const float4*)(wo1 + (k + kk) * DD + c4);
                    fma4(acc0, comp(a0, kk), b);
                    fma4(acc1, comp(a1, kk), b);
                }
            }
            float4 bb = *(const float4*)(BO1s + c4);
            float4 o0, o1;
            o0.x = sspf(acc0.x + bb.x); o0.y = sspf(acc0.y + bb.y);
            o0.z = sspf(acc0.z + bb.z); o0.w = sspf(acc0.w + bb.w);
            o1.x = sspf(acc1.x + bb.x); o1.y = sspf(acc1.y + bb.y);
            o1.z = sspf(acc1.z + bb.z); o1.w = sspf(acc1.w + bb.w);
            *(float4*)(T1f + r0 * DD + c4)       = o0;
            *(float4*)(T1f + (r0 + 1) * DD + c4) = o1;
        }
        __syncthreads();
        // f2out p2 + residual: x += t1 @ Wo2 + bo2
        {
            const float* wo2 = Wo2 + l * DD * DD;
            const int r0 = w * 2;
            float4 acc0 = {0,0,0,0}, acc1 = {0,0,0,0};
            #pragma unroll 4
            for (int k = 0; k < DD; k += 4) {
                float4 a0 = *(const float4*)(T1f + r0 * DD + k);
                float4 a1 = *(const float4*)(T1f + (r0 + 1) * DD + k);
                #pragma unroll
                for (int kk = 0; kk < 4; kk++) {
                    float4 b = *(const float4*)(wo2 + (k + kk) * DD + c4);
                    fma4(acc0, comp(a0, kk), b);
                    fma4(acc1, comp(a1, kk), b);
                }
            }
            float4 bb = *(const float4*)(BO2s + c4);
            float4 x0 = *(const float4*)(Xs + r0 * DD + c4);
            float4 x1 = *(const float4*)(Xs + (r0 + 1) * DD + c4);
            x0.x += acc0.x + bb.x; x0.y += acc0.y + bb.y;
            x0.z += acc0.z + bb.z; x0.w += acc0.w + bb.w;
            x1.x += acc1.x + bb.x; x1.y += acc1.y + bb.y;
            x1.z += acc1.z + bb.z; x1.w += acc1.w + bb.w;
            *(float4*)(Xs + r0 * DD + c4)       = x0;
            *(float4*)(Xs + (r0 + 1) * DD + c4) = x1;
        }
        __syncthreads();
    }

    // ---------- readout head ----------
    if (tid < DD) {
        float s = 0.f;
        #pragma unroll
        for (int i = 0; i < NA; i++) s += Xs[i * DD + tid];
        AGGf[tid] = s;
    }
    __syncthreads();
    if (tid < DD) {
        float acc = 0.f;
        #pragma unroll 8
        for (int k = 0; k < DD; k++) acc = fmaf(AGGf[k], Wh1[k * DD + tid], acc);
        float hpre = acc + bh1[tid];
        float h = hpre / (1.f + __expf(-hpre));   // silu
        T1f[tid] = h * Wh2[tid];
    }
    __syncthreads();
    if (tid == 0) {
        float s = bh2[0];
        #pragma unroll 8
        for (int k = 0; k < DD; k++) s += T1f[k];
        out[mol] = s;
    }
}

extern "C" void kernel_launch(void* const* d_in, const int* in_sizes, int n_in,
                              void* d_out, int out_size)
{
    const int*   Z   = (const int*)  d_in[0];
    const float* pos = (const float*)d_in[1];
    const float* emb = (const float*)d_in[6];
    const float* Wi  = (const float*)d_in[7];
    const float* Wf1 = (const float*)d_in[8];
    const float* bf1 = (const float*)d_in[9];
    const float* Wf2 = (const float*)d_in[10];
    const float* bf2 = (const float*)d_in[11];
    const float* Wo1 = (const float*)d_in[12];
    const float* bo1 = (const float*)d_in[13];
    const float* Wo2 = (const float*)d_in[14];
    const float* bo2 = (const float*)d_in[15];
    const float* Wh1 = (const float*)d_in[16];
    const float* bh1 = (const float*)d_in[17];
    const float* Wh2 = (const float*)d_in[18];
    const float* bh2 = (const float*)d_in[19];

    const int B = out_size;
    cudaFuncSetAttribute(schnet_hmma,
                         cudaFuncAttributeMaxDynamicSharedMemorySize, SMEM_BYTES);
    schnet_hmma<<<B, NB, SMEM_BYTES>>>(Z, pos, emb, Wi, Wf1, bf1, Wf2, bf2,
                                       Wo1, bo1, Wo2, bo2, Wh1, bh1, Wh2, bh2,
                                       (float*)d_out);
}

// round 4
// speedup vs baseline: 4.5806x; 2.9370x over previous
#include <cuda_runtime.h>
#include <cstdint>

#define NB 512
constexpr int NA = 32;      // atoms / molecule
constexpr int DD = 128;     // feature dim
constexpr int RR = 50;      // n_rbf
constexpr int NP = 496;     // unordered pairs
constexpr int NLAY = 6;
constexpr int TKNOTS = 4096;
constexpr int TILE = 248;   // pairs per tile (2 tiles)
constexpr float CUTOFF = 5.0f;
constexpr float WIDTH  = CUTOFF / (RR - 1);
constexpr float COEFF  = -0.5f / (WIDTH * WIDTH);
constexpr float LN2    = 0.69314718055994531f;
constexpr float PIF    = 3.14159265358979323846f;
constexpr float HSTEP  = CUTOFF / (TKNOTS - 1);
constexpr float KSCALE = (TKNOTS - 1) / CUTOFF;
constexpr int WSTR = 132;   // Ws row stride (floats)

// filter table: [layer][knot][channel]
__device__ float g_tab[(size_t)NLAY * TKNOTS * DD];

// ---------------- helpers ----------------
__device__ __forceinline__ float sspf(float x) {   // softplus(x) - ln2
    float r = __logf(fmaf(0.5f, __expf(x), 0.5f));
    return (x > 20.f) ? x - LN2 : r;
}
__device__ __forceinline__ void fma4(float4& a, float s, const float4& b) {
    a.x = fmaf(s, b.x, a.x); a.y = fmaf(s, b.y, a.y);
    a.z = fmaf(s, b.z, a.z); a.w = fmaf(s, b.w, a.w);
}
__device__ __forceinline__ void fma4v(float4& a, const float4& s, const float4& b) {
    a.x = fmaf(s.x, b.x, a.x); a.y = fmaf(s.y, b.y, a.y);
    a.z = fmaf(s.z, b.z, a.z); a.w = fmaf(s.w, b.w, a.w);
}
__device__ __forceinline__ float comp(const float4& v, int k) { return ((const float*)&v)[k]; }

// ================= kernel A: build filter table =================
// grid (32, 6): 128 knots per CTA, one layer per blockIdx.y. 256 threads.
constexpr int A_W1 = 0;          // 52x128
constexpr int A_W2 = 6656;       // 128x128
constexpr int A_F  = 23040;      // 128x52
constexpr int A_H1 = 29696;      // 128x128
constexpr int A_B1 = 46080;      // 128
constexpr int A_B2 = 46208;      // 128
constexpr int A_FLOATS = 46336;  // 185344 bytes

__global__ void __launch_bounds__(256, 1)
build_table(const float* __restrict__ Wf1, const float* __restrict__ bf1,
            const float* __restrict__ Wf2, const float* __restrict__ bf2)
{
    extern __shared__ float sa[];
    const int tid = threadIdx.x, lane = tid & 31, w = tid >> 5;  // 8 warps
    const int layer = blockIdx.y;
    const int kb = blockIdx.x * 128;
    const int c4 = lane << 2;

    for (int idx = tid; idx < 52 * 128; idx += 256) {
        int k = idx >> 7, n = idx & 127;
        sa[A_W1 + idx] = (k < RR) ? Wf1[layer * RR * DD + k * DD + n] : 0.f;
    }
    for (int idx = tid; idx < 128 * 128; idx += 256)
        sa[A_W2 + idx] = Wf2[layer * DD * DD + idx];
    if (tid < 128) {
        sa[A_B1 + tid] = bf1[layer * DD + tid];
        sa[A_B2 + tid] = bf2[layer * DD + tid];
    }
    for (int idx = tid; idx < 128 * 52; idx += 256) {
        int row = idx / 52, r = idx - row * 52;
        float d = (float)(kb + row) * HSTEP;
        float t = d - (float)r * WIDTH;
        sa[A_F + idx] = (r < RR) ? __expf(COEFF * t * t) : 0.f;
    }
    __syncthreads();

    // GEMM1: H1 = ssp(F @ W1 + b1);  8 warps x 16 rows (4 blocks of 4)
    for (int blk = 0; blk < 4; blk++) {
        const int r0 = w * 16 + blk * 4;
        float4 ac0 = {0,0,0,0}, ac1 = {0,0,0,0}, ac2 = {0,0,0,0}, ac3 = {0,0,0,0};
        #pragma unroll
        for (int k = 0; k < 52; k += 4) {
            float4 a0 = *(const float4*)(sa + A_F + (r0 + 0) * 52 + k);
            float4 a1 = *(const float4*)(sa + A_F + (r0 + 1) * 52 + k);
            float4 a2 = *(const float4*)(sa + A_F + (r0 + 2) * 52 + k);
            float4 a3 = *(const float4*)(sa + A_F + (r0 + 3) * 52 + k);
            #pragma unroll
            for (int kk = 0; kk < 4; kk++) {
                float4 b = *(const float4*)(sa + A_W1 + (k + kk) * 128 + c4);
                fma4(ac0, comp(a0, kk), b); fma4(ac1, comp(a1, kk), b);
                fma4(ac2, comp(a2, kk), b); fma4(ac3, comp(a3, kk), b);
            }
        }
        float4 bb = *(const float4*)(sa + A_B1 + c4);
        float4* accs[4] = {&ac0, &ac1, &ac2, &ac3};
        #pragma unroll
        for (int m = 0; m < 4; m++) {
            float4 o;
            o.x = sspf(accs[m]->x + bb.x); o.y = sspf(accs[m]->y + bb.y);
            o.z = sspf(accs[m]->z + bb.z); o.w = sspf(accs[m]->w + bb.w);
            *(float4*)(sa + A_H1 + (r0 + m) * 128 + c4) = o;
        }
    }
    __syncthreads();

    // GEMM2: W = (H1 @ W2 + b2) * rcut(d) -> g_tab
    for (int blk = 0; blk < 4; blk++) {
        const int r0 = w * 16 + blk * 4;
        float4 ac0 = {0,0,0,0}, ac1 = {0,0,0,0}, ac2 = {0,0,0,0}, ac3 = {0,0,0,0};
        #pragma unroll 4
        for (int k = 0; k < 128; k += 4) {
            float4 a0 = *(const float4*)(sa + A_H1 + (r0 + 0) * 128 + k);
            float4 a1 = *(const float4*)(sa + A_H1 + (r0 + 1) * 128 + k);
            float4 a2 = *(const float4*)(sa + A_H1 + (r0 + 2) * 128 + k);
            float4 a3 = *(const float4*)(sa + A_H1 + (r0 + 3) * 128 + k);
            #pragma unroll
            for (int kk = 0; kk < 4; kk++) {
                float4 b = *(const float4*)(sa + A_W2 + (k + kk) * 128 + c4);
                fma4(ac0, comp(a0, kk), b); fma4(ac1, comp(a1, kk), b);
                fma4(ac2, comp(a2, kk), b); fma4(ac3, comp(a3, kk), b);
            }
        }
        float4 bb = *(const float4*)(sa + A_B2 + c4);
        float4* accs[4] = {&ac0, &ac1, &ac2, &ac3};
        #pragma unroll
        for (int m = 0; m < 4; m++) {
            int row = r0 + m;
            float d = (float)(kb + row) * HSTEP;
            float rc = (d < CUTOFF) ? 0.5f * (__cosf(d * (PIF / CUTOFF)) + 1.f) : 0.f;
            float4 o;
            o.x = (accs[m]->x + bb.x) * rc; o.y = (accs[m]->y + bb.y) * rc;
            o.z = (accs[m]->z + bb.z) * rc; o.w = (accs[m]->w + bb.w) * rc;
            *(float4*)(g_tab + ((size_t)layer * TKNOTS + kb + row) * DD + c4) = o;
        }
    }
}

// ================= kernel B: main network =================
// smem float offsets
constexpr int OFF_WS   = 0;        // 248 x 132 = 32736
constexpr int OFF_X    = 32736;    // 32x128
constexpr int OFF_XF   = 36832;
constexpr int OFF_AGG  = 40928;
constexpr int OFF_T1   = 45024;
constexpr int OFF_FRAC = 49120;    // 512 f32 (496 used)
constexpr int OFF_BO1  = 49632;    // 128
constexpr int OFF_BO2  = 49760;    // 128
constexpr int OFF_POS  = 49888;    // 96
constexpr int OFF_KNOT = 49984;    // 512 u16 = 256 f
constexpr int OFF_PAIR = 50240;    // 512 u16 = 256 f
constexpr int OFF_LIST = 50496;    // 992 u16 -> 512 f
constexpr int B_FLOATS = 51008;    // 204032 bytes

__global__ void __launch_bounds__(NB, 1)
schnet_main(const int*   __restrict__ Z,   const float* __restrict__ pos,
            const float* __restrict__ emb, const float* __restrict__ Wi,
            const float* __restrict__ Wo1, const float* __restrict__ bo1,
            const float* __restrict__ Wo2, const float* __restrict__ bo2,
            const float* __restrict__ Wh1, const float* __restrict__ bh1,
            const float* __restrict__ Wh2, const float* __restrict__ bh2,
            float* __restrict__ out)
{
    extern __shared__ float sm[];
    float* Wsf   = sm + OFF_WS;
    float* Xs    = sm + OFF_X;
    float* XFs   = sm + OFF_XF;
    float* AGGf  = sm + OFF_AGG;
    float* T1f   = sm + OFF_T1;
    float* FRACs = sm + OFF_FRAC;
    float* BO1s  = sm + OFF_BO1;
    float* BO2s  = sm + OFF_BO2;
    float* POSs  = sm + OFF_POS;
    unsigned short* KNOTs = (unsigned short*)(sm + OFF_KNOT);
    unsigned short* PAIRs = (unsigned short*)(sm + OFF_PAIR);
    unsigned short* LISTs = (unsigned short*)(sm + OFF_LIST);

    const int tid = threadIdx.x, lane = tid & 31, w = tid >> 5;  // 16 warps
    const int mol = blockIdx.x;
    const int c4 = lane << 2;

    // ---------- init ----------
    if (tid < NA * 3) POSs[tid] = pos[mol * NA * 3 + tid];
    {
        int p = tid;
        unsigned short pr = 0;
        if (p < NP) {
            int i = 0, base = 0;
            while (p >= base + (31 - i)) { base += 31 - i; i++; }
            int j = i + 1 + (p - base);
            pr = (unsigned short)((i << 5) | j);
        }
        PAIRs[tid] = pr;
    }
    for (int idx = tid; idx < NA * DD; idx += NB) {
        int a = idx >> 7, cc = idx & (DD - 1);
        Xs[idx] = emb[Z[mol * NA + a] * DD + cc];
    }
    if (tid < NA) {   // per-atom partner lists, sorted by pair index
        int a = tid, e = 0;
        for (int i = 0; i < a; i++) {
            int p = i * 31 - (i * (i - 1)) / 2 + (a - i - 1);
            LISTs[a * 31 + e++] = (unsigned short)(p | (i << 10));
        }
        for (int j = a + 1; j < NA; j++) {
            int p = a * 31 - (a * (a - 1)) / 2 + (j - a - 1);
            LISTs[a * 31 + e++] = (unsigned short)(p | (j << 10));
        }
    }
    __syncthreads();
    if (tid < NP) {
        int pr = PAIRs[tid]; int i = pr >> 5, j = pr & 31;
        float dx = POSs[i*3+0] - POSs[j*3+0];
        float dy = POSs[i*3+1] - POSs[j*3+1];
        float dz = POSs[i*3+2] - POSs[j*3+2];
        float d = sqrtf(dx*dx + dy*dy + dz*dz);
        float t = fminf(d * KSCALE, (float)(TKNOTS - 1));
        int kf = min((int)t, TKNOTS - 2);
        KNOTs[tid] = (unsigned short)kf;
        FRACs[tid] = t - (float)kf;
    }
    __syncthreads();

    // ---------- interaction layers ----------
    for (int l = 0; l < NLAY; l++) {
        if (tid < DD) {
            BO1s[tid] = bo1[l * DD + tid];
            BO2s[tid] = bo2[l * DD + tid];
        }
        // in2f: xf = x @ Wi[l]   (16 warps x 2 rows)
        {
            const float* wi = Wi + l * DD * DD;
            const int r0 = w * 2;
            float4 acc0 = {0,0,0,0}, acc1 = {0,0,0,0};
            #pragma unroll 4
            for (int k = 0; k < DD; k += 4) {
                float4 a0 = *(const float4*)(Xs + r0 * DD + k);
                float4 a1 = *(const float4*)(Xs + (r0 + 1) * DD + k);
                #pragma unroll
                for (int kk = 0; kk < 4; kk++) {
                    float4 b = *(const float4*)(wi + (k + kk) * DD + c4);
                    fma4(acc0, comp(a0, kk), b);
                    fma4(acc1, comp(a1, kk), b);
                }
            }
            *(float4*)(XFs + r0 * DD + c4)       = acc0;
            *(float4*)(XFs + (r0 + 1) * DD + c4) = acc1;
        }
        __syncthreads();

        float4 accB0 = {0,0,0,0}, accB1 = {0,0,0,0};   // msg acc: atoms w, w+16
        int e0 = 0, e1 = 0;                             // list cursors
        const float* tabL = g_tab + (size_t)l * TKNOTS * DD;

        for (int t = 0; t < 2; t++) {
            // ---- gather W for this tile via table lerp ----
            for (int idx = tid; idx < TILE * 32; idx += NB) {
                int pl = idx >> 5, cg = idx & 31;
                int p  = t * TILE + pl;
                int k  = KNOTs[p];
                float f = FRACs[p];
                const float4* tp = (const float4*)(tabL + (size_t)k * DD) + cg;
                float4 a = tp[0];
                float4 b = tp[DD / 4];
                float4 o;
                o.x = fmaf(f, b.x - a.x, a.x);
                o.y = fmaf(f, b.y - a.y, a.y);
                o.z = fmaf(f, b.z - a.z, a.z);
                o.w = fmaf(f, b.w - a.w, a.w);
                *(float4*)(Wsf + pl * WSTR + cg * 4) = o;
            }
            __syncthreads();
            // ---- message accumulate via per-atom lists ----
            {
                const int end = (t + 1) * TILE, base = t * TILE;
                const int a0 = w, a1 = w + 16;
                while (e0 < 31) {
                    int ent = LISTs[a0 * 31 + e0];
                    int p = ent & 1023;
                    if (p >= end) break;
                    int other = ent >> 10;
                    float4 wv = *(const float4*)(Wsf + (p - base) * WSTR + c4);
                    float4 xv = *(const float4*)(XFs + other * DD + c4);
                    fma4v(accB0, wv, xv);
                    e0++;
                }
                while (e1 < 31) {
                    int ent = LISTs[a1 * 31 + e1];
                    int p = ent & 1023;
                    if (p >= end) break;
                    int other = ent >> 10;
                    float4 wv = *(const float4*)(Wsf + (p - base) * WSTR + c4);
                    float4 xv = *(const float4*)(XFs + other * DD + c4);
                    fma4v(accB1, wv, xv);
                    e1++;
                }
            }
            __syncthreads();
        }
        *(float4*)(AGGf + w * DD + c4)        = accB0;
        *(float4*)(AGGf + (w + 16) * DD + c4) = accB1;
        __syncthreads();
        // f2out p1: t1 = ssp(agg @ Wo1 + bo1)
        {
            const float* wo1 = Wo1 + l * DD * DD;
            const int r0 = w * 2;
            float4 acc0 = {0,0,0,0}, acc1 = {0,0,0,0};
            #pragma unroll 4
            for (int k = 0; k < DD; k += 4) {
                float4 a0 = *(const float4*)(AGGf + r0 * DD + k);
                float4 a1 = *(const float4*)(AGGf + (r0 + 1) * DD + k);
                #pragma unroll
                for (int kk = 0; kk < 4; kk++) {
                    float4 b = *(const float4*)(wo1 + (k + kk) * DD + c4);
                    fma4(acc0, comp(a0, kk), b);
                    fma4(acc1, comp(a1, kk), b);
                }
            }
            float4 bb = *(const float4*)(BO1s + c4);
            float4 o0, o1;
            o0.x = sspf(acc0.x + bb.x); o0.y = sspf(acc0.y + bb.y);
            o0.z = sspf(acc0.z + bb.z); o0.w = sspf(acc0.w + bb.w);
            o1.x = sspf(acc1.x + bb.x); o1.y = sspf(acc1.y + bb.y);
            o1.z = sspf(acc1.z + bb.z); o1.w = sspf(acc1.w + bb.w);
            *(float4*)(T1f + r0 * DD + c4)       = o0;
            *(float4*)(T1f + (r0 + 1) * DD + c4) = o1;
        }
        __syncthreads();
        // f2out p2 + residual: x += t1 @ Wo2 + bo2
        {
            const float* wo2 = Wo2 + l * DD * DD;
            const int r0 = w * 2;
            float4 acc0 = {0,0,0,0}, acc1 = {0,0,0,0};
            #pragma unroll 4
            for (int k = 0; k < DD; k += 4) {
                float4 a0 = *(const float4*)(T1f + r0 * DD + k);
                float4 a1 = *(const float4*)(T1f + (r0 + 1) * DD + k);
                #pragma unroll
                for (int kk = 0; kk < 4; kk++) {
                    float4 b = *(const float4*)(wo2 + (k + kk) * DD + c4);
                    fma4(acc0, comp(a0, kk), b);
                    fma4(acc1, comp(a1, kk), b);
                }
            }
            float4 bb = *(const float4*)(BO2s + c4);
            float4 x0 = *(const float4*)(Xs + r0 * DD + c4);
            float4 x1 = *(const float4*)(Xs + (r0 + 1) * DD + c4);
            x0.x += acc0.x + bb.x; x0.y += acc0.y + bb.y;
            x0.z += acc0.z + bb.z; x0.w += acc0.w + bb.w;
            x1.x += acc1.x + bb.x; x1.y += acc1.y + bb.y;
            x1.z += acc1.z + bb.z; x1.w += acc1.w + bb.w;
            *(float4*)(Xs + r0 * DD + c4)       = x0;
            *(float4*)(Xs + (r0 + 1) * DD + c4) = x1;
        }
        __syncthreads();
    }

    // ---------- readout head ----------
    if (tid < DD) {
        float s = 0.f;
        #pragma unroll
        for (int i = 0; i < NA; i++) s += Xs[i * DD + tid];
        AGGf[tid] = s;
    }
    __syncthreads();
    if (tid < DD) {
        float acc = 0.f;
        #pragma unroll 8
        for (int k = 0; k < DD; k++) acc = fmaf(AGGf[k], Wh1[k * DD + tid], acc);
        float hpre = acc + bh1[tid];
        float h = hpre / (1.f + __expf(-hpre));   // silu
        T1f[tid] = h * Wh2[tid];
    }
    __syncthreads();
    if (tid == 0) {
        float s = bh2[0];
        #pragma unroll 8
        for (int k = 0; k < DD; k++) s += T1f[k];
        out[mol] = s;
    }
}

extern "C" void kernel_launch(void* const* d_in, const int* in_sizes, int n_in,
                              void* d_out, int out_size)
{
    const int*   Z   = (const int*)  d_in[0];
    const float* pos = (const float*)d_in[1];
    const float* emb = (const float*)d_in[6];
    const float* Wi  = (const float*)d_in[7];
    const float* Wf1 = (const float*)d_in[8];
    const float* bf1 = (const float*)d_in[9];
    const float* Wf2 = (const float*)d_in[10];
    const float* bf2 = (const float*)d_in[11];
    const float* Wo1 = (const float*)d_in[12];
    const float* bo1 = (const float*)d_in[13];
    const float* Wo2 = (const float*)d_in[14];
    const float* bo2 = (const float*)d_in[15];
    const float* Wh1 = (const float*)d_in[16];
    const float* bh1 = (const float*)d_in[17];
    const float* Wh2 = (const float*)d_in[18];
    const float* bh2 = (const float*)d_in[19];

    const int B = out_size;
    const int smemA = A_FLOATS * sizeof(float);
    const int smemB = B_FLOATS * sizeof(float);
    cudaFuncSetAttribute(build_table,
                         cudaFuncAttributeMaxDynamicSharedMemorySize, smemA);
    cudaFuncSetAttribute(schnet_main,
                         cudaFuncAttributeMaxDynamicSharedMemorySize, smemB);

    build_table<<<dim3(TKNOTS / 128, NLAY), 256, smemA>>>(Wf1, bf1, Wf2, bf2);
    schnet_main<<<B, NB, smemB>>>(Z, pos, emb, Wi, Wo1, bo1, Wo2, bo2,
                                  Wh1, bh1, Wh2, bh2, (float*)d_out);
}

// round 6
// speedup vs baseline: 5.8716x; 1.2818x over previous
#include <cuda_runtime.h>
#include <cuda_bf16.h>
#include <cstdint>

#define NB 512
constexpr int NA = 32;
constexpr int DD = 128;
constexpr int RR = 50;
constexpr int NP = 496;
constexpr int NLAY = 6;
constexpr int TKNOTS = 4096;
constexpr int TILE = 124;    // pairs per tile
constexpr int NTILE = 4;
constexpr float CUTOFF = 5.0f;
constexpr float WIDTH  = CUTOFF / (RR - 1);
constexpr float COEFF  = -0.5f / (WIDTH * WIDTH);
constexpr float LN2    = 0.69314718055994531f;
constexpr float PIF    = 3.14159265358979323846f;
constexpr float HSTEP  = CUTOFF / (TKNOTS - 1);
constexpr float KSCALE = (TKNOTS - 1) / CUTOFF;
constexpr int WSTR = 132;    // Ws row stride (floats)
constexpr int BSTR = 272;    // bf16 operand row stride (bytes) = 136 halves

// ---------------- device globals ----------------
__device__ float    g_tab[(size_t)NLAY * TKNOTS * DD];            // fp32 filter table
__device__ uint32_t g_wh[3 * NLAY * DD * (DD / 2)];               // bf16-hi packed pairs
__device__ uint32_t g_wl[3 * NLAY * DD * (DD / 2)];               // bf16-lo packed pairs

// ---------------- helpers ----------------
__device__ __forceinline__ uint32_t smem_u32(const void* p) {
    uint32_t a;
    asm("{ .reg .u64 t; cvta.to.shared.u64 t, %1; cvt.u32.u64 %0, t; }"
        : "=r"(a) : "l"(p));
    return a;
}
__device__ __forceinline__ void ldsm4(uint32_t* r, uint32_t a) {
    asm volatile("ldmatrix.sync.aligned.m8n8.x4.shared.b16 {%0,%1,%2,%3}, [%4];"
        : "=r"(r[0]), "=r"(r[1]), "=r"(r[2]), "=r"(r[3]) : "r"(a));
}
__device__ __forceinline__ void ldsm4t(uint32_t* r, uint32_t a) {
    asm volatile("ldmatrix.sync.aligned.m8n8.x4.trans.shared.b16 {%0,%1,%2,%3}, [%4];"
        : "=r"(r[0]), "=r"(r[1]), "=r"(r[2]), "=r"(r[3]) : "r"(a));
}
__device__ __forceinline__ void mmabf(float* c, const uint32_t* a, const uint32_t* b) {
    asm volatile("mma.sync.aligned.m16n8k16.row.col.f32.bf16.bf16.f32 "
        "{%0,%1,%2,%3}, {%4,%5,%6,%7}, {%8,%9}, {%0,%1,%2,%3};"
        : "+f"(c[0]), "+f"(c[1]), "+f"(c[2]), "+f"(c[3])
        : "r"(a[0]), "r"(a[1]), "r"(a[2]), "r"(a[3]), "r"(b[0]), "r"(b[1]));
}
__device__ __forceinline__ void split2(float x, uint32_t& h, uint32_t& l) {
    __nv_bfloat16 hb = __float2bfloat16(x);
    __nv_bfloat16 lb = __float2bfloat16(x - __bfloat162float(hb));
    h = (uint32_t)__bfloat16_as_ushort(hb);
    l = (uint32_t)__bfloat16_as_ushort(lb);
}
__device__ __forceinline__ float sspf(float x) {
    float r = __logf(fmaf(0.5f, __expf(x), 0.5f));
    return (x > 20.f) ? x - LN2 : r;
}
__device__ __forceinline__ void fma4(float4& a, float s, const float4& b) {
    a.x = fmaf(s, b.x, a.x); a.y = fmaf(s, b.y, a.y);
    a.z = fmaf(s, b.z, a.z); a.w = fmaf(s, b.w, a.w);
}
__device__ __forceinline__ void fma4v(float4& a, const float4& s, const float4& b) {
    a.x = fmaf(s.x, b.x, a.x); a.y = fmaf(s.y, b.y, a.y);
    a.z = fmaf(s.z, b.z, a.z); a.w = fmaf(s.w, b.w, a.w);
}
__device__ __forceinline__ float comp(const float4& v, int k) { return ((const float*)&v)[k]; }

// 16x16 output warp tile, K=16*KS, 3-pass split-bf16. A[m][k] stride BSTR, B[k][n] stride BSTR.
template<int KS>
__device__ __forceinline__ void gemm16(
    uint32_t aH, uint32_t aL, uint32_t bH, uint32_t bL,
    int mr, int nc, int lane, float (*c)[4])
{
    const uint32_t aoff = (uint32_t)((mr + (lane & 7) + ((lane >> 3) & 1) * 8) * BSTR
                                     + ((lane >> 4) & 1) * 16);
    const uint32_t boff = (uint32_t)(((lane & 7) + ((lane >> 3) & 1) * 8) * BSTR
                                     + (nc + ((lane >> 4) & 1) * 8) * 2);
    #pragma unroll
    for (int ks = 0; ks < KS; ks++) {
        const uint32_t ao = aoff + ks * 32;
        const uint32_t bo = boff + ks * 16 * BSTR;
        uint32_t Ah[4], Al[4], Bh[4], Bl[4];
        ldsm4(Ah, aH + ao);
        ldsm4t(Bh, bH + bo);
        mmabf(c[0], Ah, Bh); mmabf(c[1], Ah, Bh + 2);
        ldsm4t(Bl, bL + bo);
        mmabf(c[0], Ah, Bl); mmabf(c[1], Ah, Bl + 2);
        ldsm4(Al, aL + ao);
        mmabf(c[0], Al, Bh); mmabf(c[1], Al, Bh + 2);
    }
}

// ================= builder 1: filter table (fp32) =================
constexpr int A_W1 = 0;          // 52x128
constexpr int A_W2 = 6656;       // 128x128
constexpr int A_F  = 23040;      // 128x52
constexpr int A_H1 = 29696;      // 128x128
constexpr int A_B1 = 46080;
constexpr int A_B2 = 46208;
constexpr int A_FLOATS = 46336;

__global__ void __launch_bounds__(256, 1)
build_table(const float* __restrict__ Wf1, const float* __restrict__ bf1,
            const float* __restrict__ Wf2, const float* __restrict__ bf2)
{
    extern __shared__ float sa[];
    const int tid = threadIdx.x, lane = tid & 31, w = tid >> 5;
    const int layer = blockIdx.y;
    const int kb = blockIdx.x * 128;
    const int c4 = lane << 2;

    for (int idx = tid; idx < 52 * 128; idx += 256) {
        int k = idx >> 7, n = idx & 127;
        sa[A_W1 + idx] = (k < RR) ? Wf1[layer * RR * DD + k * DD + n] : 0.f;
    }
    for (int idx = tid; idx < 128 * 128; idx += 256)
        sa[A_W2 + idx] = Wf2[layer * DD * DD + idx];
    if (tid < 128) {
        sa[A_B1 + tid] = bf1[layer * DD + tid];
        sa[A_B2 + tid] = bf2[layer * DD + tid];
    }
    for (int idx = tid; idx < 128 * 52; idx += 256) {
        int row = idx / 52, r = idx - row * 52;
        float d = (float)(kb + row) * HSTEP;
        float t = d - (float)r * WIDTH;
        sa[A_F + idx] = (r < RR) ? __expf(COEFF * t * t) : 0.f;
    }
    __syncthreads();

    for (int blk = 0; blk < 4; blk++) {
        const int r0 = w * 16 + blk * 4;
        float4 ac0 = {0,0,0,0}, ac1 = {0,0,0,0}, ac2 = {0,0,0,0}, ac3 = {0,0,0,0};
        #pragma unroll
        for (int k = 0; k < 52; k += 4) {
            float4 a0 = *(const float4*)(sa + A_F + (r0 + 0) * 52 + k);
            float4 a1 = *(const float4*)(sa + A_F + (r0 + 1) * 52 + k);
            float4 a2 = *(const float4*)(sa + A_F + (r0 + 2) * 52 + k);
            float4 a3 = *(const float4*)(sa + A_F + (r0 + 3) * 52 + k);
            #pragma unroll
            for (int kk = 0; kk < 4; kk++) {
                float4 b = *(const float4*)(sa + A_W1 + (k + kk) * 128 + c4);
                fma4(ac0, comp(a0, kk), b); fma4(ac1, comp(a1, kk), b);
                fma4(ac2, comp(a2, kk), b); fma4(ac3, comp(a3, kk), b);
            }
        }
        float4 bb = *(const float4*)(sa + A_B1 + c4);
        float4* accs[4] = {&ac0, &ac1, &ac2, &ac3};
        #pragma unroll
        for (int m = 0; m < 4; m++) {
            float4 o;
            o.x = sspf(accs[m]->x + bb.x); o.y = sspf(accs[m]->y + bb.y);
            o.z = sspf(accs[m]->z + bb.z); o.w = sspf(accs[m]->w + bb.w);
            *(float4*)(sa + A_H1 + (r0 + m) * 128 + c4) = o;
        }
    }
    __syncthreads();

    for (int blk = 0; blk < 4; blk++) {
        const int r0 = w * 16 + blk * 4;
        float4 ac0 = {0,0,0,0}, ac1 = {0,0,0,0}, ac2 = {0,0,0,0}, ac3 = {0,0,0,0};
        #pragma unroll 4
        for (int k = 0; k < 128; k += 4) {
            float4 a0 = *(const float4*)(sa + A_H1 + (r0 + 0) * 128 + k);
            float4 a1 = *(const float4*)(sa + A_H1 + (r0 + 1) * 128 + k);
            float4 a2 = *(const float4*)(sa + A_H1 + (r0 + 2) * 128 + k);
            float4 a3 = *(const float4*)(sa + A_H1 + (r0 + 3) * 128 + k);
            #pragma unroll
            for (int kk = 0; kk < 4; kk++) {
                float4 b = *(const float4*)(sa + A_W2 + (k + kk) * 128 + c4);
                fma4(ac0, comp(a0, kk), b); fma4(ac1, comp(a1, kk), b);
                fma4(ac2, comp(a2, kk), b); fma4(ac3, comp(a3, kk), b);
            }
        }
        float4 bb = *(const float4*)(sa + A_B2 + c4);
        float4* accs[4] = {&ac0, &ac1, &ac2, &ac3};
        #pragma unroll
        for (int m = 0; m < 4; m++) {
            int rowg = kb + r0 + m;
            float d = (float)rowg * HSTEP;
            float rc = (d < CUTOFF) ? 0.5f * (__cosf(d * (PIF / CUTOFF)) + 1.f) : 0.f;
            float4 o;
            o.x = (accs[m]->x + bb.x) * rc; o.y = (accs[m]->y + bb.y) * rc;
            o.z = (accs[m]->z + bb.z) * rc; o.w = (accs[m]->w + bb.w) * rc;
            *(float4*)(g_tab + ((size_t)layer * TKNOTS + rowg) * DD + c4) = o;
        }
    }
}

// ================= builder 2: split Wi/Wo1/Wo2 to bf16 hi/lo =================
__global__ void __launch_bounds__(1024, 1)
build_wsplit(const float* __restrict__ Wi,
             const float* __restrict__ Wo1,
             const float* __restrict__ Wo2)
{
    int idx = blockIdx.x * 1024 + threadIdx.x;     // one packed uint32 pair
    const int TOT = 3 * NLAY * DD * (DD / 2);
    if (idx >= TOT) return;
    int mat = idx / (NLAY * DD * (DD / 2));
    int rem = idx - mat * (NLAY * DD * (DD / 2));
    const float* src = (mat == 0) ? Wi : (mat == 1) ? Wo1 : Wo2;
    float v0 = src[rem * 2];
    float v1 = src[rem * 2 + 1];
    uint32_t h0, l0, h1, l1;
    split2(v0, h0, l0); split2(v1, h1, l1);
    g_wh[idx] = h0 | (h1 << 16);
    g_wl[idx] = l0 | (l1 << 16);
}

// ================= main kernel =================
constexpr int SB_WBH  = 0;         // 128 x 272B = 34816
constexpr int SB_WBL  = 34816;
constexpr int SB_WS   = 69632;     // 124 x 132 f32 = 65472
constexpr int SB_X    = 135168;    // 32x128 f32
constexpr int SB_XF   = 151552;
constexpr int SB_A1H  = 167936;    // 32 x 272B
constexpr int SB_A1L  = 176640;
constexpr int SB_A2H  = 185344;
constexpr int SB_A2L  = 194048;
constexpr int SB_BO1  = 202752;    // 128 f32
constexpr int SB_BO2  = 203264;
constexpr int SB_POS  = 203776;    // 96 f32
constexpr int SB_FRAC = 204160;    // 512 f32
constexpr int SB_KNOT = 206208;    // 512 u16
constexpr int SB_PAIR = 207232;    // 512 u16
constexpr int SB_LIST = 208256;    // 992 u16
constexpr int SMEM_BYTES = 210432;

__global__ void __launch_bounds__(NB, 1)
schnet_main(const int*   __restrict__ Z,   const float* __restrict__ pos,
            const float* __restrict__ emb,
            const float* __restrict__ bo1, const float* __restrict__ bo2,
            const float* __restrict__ Wh1, const float* __restrict__ bh1,
            const float* __restrict__ Wh2, const float* __restrict__ bh2,
            float* __restrict__ out)
{
    extern __shared__ __align__(1024) char smc[];
    float* Wsf   = (float*)(smc + SB_WS);
    float* Xs    = (float*)(smc + SB_X);
    float* XFs   = (float*)(smc + SB_XF);
    float* BO1s  = (float*)(smc + SB_BO1);
    float* BO2s  = (float*)(smc + SB_BO2);
    float* POSs  = (float*)(smc + SB_POS);
    float* FRACs = (float*)(smc + SB_FRAC);
    uint32_t* A1H32 = (uint32_t*)(smc + SB_A1H);
    uint32_t* A1L32 = (uint32_t*)(smc + SB_A1L);
    uint32_t* A2H32 = (uint32_t*)(smc + SB_A2H);
    uint32_t* A2L32 = (uint32_t*)(smc + SB_A2L);
    unsigned short* KNOTs = (unsigned short*)(smc + SB_KNOT);
    unsigned short* PAIRs = (unsigned short*)(smc + SB_PAIR);
    unsigned short* LISTs = (unsigned short*)(smc + SB_LIST);
    const uint32_t smb = smem_u32(smc);

    const int tid = threadIdx.x, lane = tid & 31, w = tid >> 5;
    const int mol = blockIdx.x;
    const int c4 = lane << 2;
    const int mr = (w & 1) * 16, nc = (w >> 1) * 16;   // HMMA warp tile

    // ---------- init ----------
    if (tid < NA * 3) POSs[tid] = pos[mol * NA * 3 + tid];
    {
        int p = tid;
        unsigned short pr = 0;
        if (p < NP) {
            int i = 0, base = 0;
            while (p >= base + (31 - i)) { base += 31 - i; i++; }
            int j = i + 1 + (p - base);
            pr = (unsigned short)((i << 5) | j);
        }
        PAIRs[tid] = pr;
    }
    for (int idx = tid; idx < NA * DD; idx += NB) {
        int a = idx >> 7, cc = idx & (DD - 1);
        Xs[idx] = emb[Z[mol * NA + a] * DD + cc];
    }
    if (tid < NA) {
        int a = tid, e = 0;
        for (int i = 0; i < a; i++) {
            int p = i * 31 - (i * (i - 1)) / 2 + (a - i - 1);
            LISTs[a * 31 + e++] = (unsigned short)(p | (i << 10));
        }
        for (int j = a + 1; j < NA; j++) {
            int p = a * 31 - (a * (a - 1)) / 2 + (j - a - 1);
            LISTs[a * 31 + e++] = (unsigned short)(p | (j << 10));
        }
    }
    __syncthreads();
    if (tid < NP) {
        int pr = PAIRs[tid]; int i = pr >> 5, j = pr & 31;
        float dx = POSs[i*3+0] - POSs[j*3+0];
        float dy = POSs[i*3+1] - POSs[j*3+1];
        float dz = POSs[i*3+2] - POSs[j*3+2];
        float d = sqrtf(dx*dx + dy*dy + dz*dz);
        float t = fminf(d * KSCALE, (float)(TKNOTS - 1));
        int kf = min((int)t, TKNOTS - 2);
        KNOTs[tid] = (unsigned short)kf;
        FRACs[tid] = t - (float)kf;
    }
    __syncthreads();

    // ---------- layers ----------
    for (int l = 0; l < NLAY; l++) {
        const int wbase = l * 4096;                       // uint2 units per matrix-layer
        // stage Wi split + split X + biases
        {
            const uint2* gh = (const uint2*)g_wh;
            const uint2* gl = (const uint2*)g_wl;
            for (int idx = tid; idx < 4096; idx += NB) {
                int row = idx >> 5, n4 = idx & 31;
                *(uint2*)(smc + SB_WBH + row * BSTR + n4 * 8) = gh[wbase + idx];
                *(uint2*)(smc + SB_WBL + row * BSTR + n4 * 8) = gl[wbase + idx];
            }
            for (int idx = tid; idx < 2048; idx += NB) {
                int row = idx >> 6, n2 = idx & 63;
                float2 v = *(const float2*)(Xs + row * DD + n2 * 2);
                uint32_t h0, l0, h1, l1;
                split2(v.x, h0, l0); split2(v.y, h1, l1);
                A1H32[row * 68 + n2] = h0 | (h1 << 16);
                A1L32[row * 68 + n2] = l0 | (l1 << 16);
            }
            if (tid < DD) {
                BO1s[tid] = bo1[l * DD + tid];
                BO2s[tid] = bo2[l * DD + tid];
            }
        }
        __syncthreads();
        // in2f HMMA -> XF ; then gather tile 0
        {
            float c[2][4] = {{0,0,0,0},{0,0,0,0}};
            gemm16<8>(smb + SB_A1H, smb + SB_A1L, smb + SB_WBH, smb + SB_WBL,
                      mr, nc, lane, c);
            int r0 = mr + (lane >> 2);
            int cb = nc + (lane & 3) * 2;
            *(float2*)(XFs + r0 * DD + cb)           = make_float2(c[0][0], c[0][1]);
            *(float2*)(XFs + (r0 + 8) * DD + cb)     = make_float2(c[0][2], c[0][3]);
            *(float2*)(XFs + r0 * DD + cb + 8)       = make_float2(c[1][0], c[1][1]);
            *(float2*)(XFs + (r0 + 8) * DD + cb + 8) = make_float2(c[1][2], c[1][3]);
        }
        const float* tabL = g_tab + (size_t)l * TKNOTS * DD;
        // gather tile 0
        for (int idx = tid; idx < TILE * 32; idx += NB) {
            int pl = idx >> 5, cg = idx & 31;
            int k = KNOTs[pl];
            float f = FRACs[pl];
            const float4* tp = (const float4*)(tabL + (size_t)k * DD) + cg;
            float4 a = tp[0];
            float4 b = tp[DD / 4];
            float4 o;
            o.x = fmaf(f, b.x - a.x, a.x); o.y = fmaf(f, b.y - a.y, a.y);
            o.z = fmaf(f, b.z - a.z, a.z); o.w = fmaf(f, b.w - a.w, a.w);
            *(float4*)(Wsf + pl * WSTR + cg * 4) = o;
        }
        __syncthreads();

        float4 accB0 = {0,0,0,0}, accB1 = {0,0,0,0};
        int e0 = 0, e1 = 0;
        for (int t = 0; t < NTILE; t++) {
            // message accumulate over tile t
            {
                const int end = (t + 1) * TILE, base = t * TILE;
                const int a0 = w, a1 = w + 16;
                while (e0 < 31) {
                    int ent = LISTs[a0 * 31 + e0];
                    int p = ent & 1023;
                    if (p >= end) break;
                    int other = ent >> 10;
                    float4 wv = *(const float4*)(Wsf + (p - base) * WSTR + c4);
                    float4 xv = *(const float4*)(XFs + other * DD + c4);
                    fma4v(accB0, wv, xv);
                    e0++;
                }
                while (e1 < 31) {
                    int ent = LISTs[a1 * 31 + e1];
                    int p = ent & 1023;
                    if (p >= end) break;
                    int other = ent >> 10;
                    float4 wv = *(const float4*)(Wsf + (p - base) * WSTR + c4);
                    float4 xv = *(const float4*)(XFs + other * DD + c4);
                    fma4v(accB1, wv, xv);
                    e1++;
                }
            }
            if (t < NTILE - 1) {
                __syncthreads();
                const int base = (t + 1) * TILE;
                for (int idx = tid; idx < TILE * 32; idx += NB) {
                    int pl = idx >> 5, cg = idx & 31;
                    int p = base + pl;
                    int k = KNOTs[p];
                    float f = FRACs[p];
                    const float4* tp = (const float4*)(tabL + (size_t)k * DD) + cg;
                    float4 a = tp[0];
                    float4 b = tp[DD / 4];
                    float4 o;
                    o.x = fmaf(f, b.x - a.x, a.x); o.y = fmaf(f, b.y - a.y, a.y);
                    o.z = fmaf(f, b.z - a.z, a.z); o.w = fmaf(f, b.w - a.w, a.w);
                    *(float4*)(Wsf + pl * WSTR + cg * 4) = o;
                }
                __syncthreads();
            }
        }
        // dump agg split to A1 + stage Wo1
        {
            uint32_t h0,l0,h1,l1,h2,l2,h3,l3;
            split2(accB0.x, h0, l0); split2(accB0.y, h1, l1);
            split2(accB0.z, h2, l2); split2(accB0.w, h3, l3);
            A1H32[w * 68 + lane * 2]     = h0 | (h1 << 16);
            A1H32[w * 68 + lane * 2 + 1] = h2 | (h3 << 16);
            A1L32[w * 68 + lane * 2]     = l0 | (l1 << 16);
            A1L32[w * 68 + lane * 2 + 1] = l2 | (l3 << 16);
            split2(accB1.x, h0, l0); split2(accB1.y, h1, l1);
            split2(accB1.z, h2, l2); split2(accB1.w, h3, l3);
            A1H32[(w + 16) * 68 + lane * 2]     = h0 | (h1 << 16);
            A1H32[(w + 16) * 68 + lane * 2 + 1] = h2 | (h3 << 16);
            A1L32[(w + 16) * 68 + lane * 2]     = l0 | (l1 << 16);
            A1L32[(w + 16) * 68 + lane * 2 + 1] = l2 | (l3 << 16);
            const uint2* gh = (const uint2*)g_wh;
            const uint2* gl = (const uint2*)g_wl;
            const int wb1 = (NLAY + l) * 4096;
            for (int idx = tid; idx < 4096; idx += NB) {
                int row = idx >> 5, n4 = idx & 31;
                *(uint2*)(smc + SB_WBH + row * BSTR + n4 * 8) = gh[wb1 + idx];
                *(uint2*)(smc + SB_WBL + row * BSTR + n4 * 8) = gl[wb1 + idx];
            }
        }
        __syncthreads();
        // f2out1: t1 = ssp(agg @ Wo1 + bo1) -> split -> A2
        {
            float c[2][4] = {{0,0,0,0},{0,0,0,0}};
            gemm16<8>(smb + SB_A1H, smb + SB_A1L, smb + SB_WBH, smb + SB_WBL,
                      mr, nc, lane, c);
            int r0 = mr + (lane >> 2);
            int cb = nc + (lane & 3) * 2;
            #pragma unroll
            for (int ni = 0; ni < 2; ni++)
                #pragma unroll
                for (int h = 0; h < 2; h++) {
                    int row = r0 + h * 8, col = cb + ni * 8;
                    float v0 = sspf(c[ni][h*2+0] + BO1s[col]);
                    float v1 = sspf(c[ni][h*2+1] + BO1s[col+1]);
                    uint32_t h0,l0,h1,l1;
                    split2(v0, h0, l0); split2(v1, h1, l1);
                    A2H32[row * 68 + (col >> 1)] = h0 | (h1 << 16);
                    A2L32[row * 68 + (col >> 1)] = l0 | (l1 << 16);
                }
        }
        __syncthreads();
        // stage Wo2
        {
            const uint2* gh = (const uint2*)g_wh;
            const uint2* gl = (const uint2*)g_wl;
            const int wb2 = (2 * NLAY + l) * 4096;
            for (int idx = tid; idx < 4096; idx += NB) {
                int row = idx >> 5, n4 = idx & 31;
                *(uint2*)(smc + SB_WBH + row * BSTR + n4 * 8) = gh[wb2 + idx];
                *(uint2*)(smc + SB_WBL + row * BSTR + n4 * 8) = gl[wb2 + idx];
            }
        }
        __syncthreads();
        // f2out2 + residual: x += t1 @ Wo2 + bo2
        {
            float c[2][4] = {{0,0,0,0},{0,0,0,0}};
            gemm16<8>(smb + SB_A2H, smb + SB_A2L, smb + SB_WBH, smb + SB_WBL,
                      mr, nc, lane, c);
            int r0 = mr + (lane >> 2);
            int cb = nc + (lane & 3) * 2;
            #pragma unroll
            for (int ni = 0; ni < 2; ni++)
                #pragma unroll
                for (int h = 0; h < 2; h++) {
                    int row = r0 + h * 8, col = cb + ni * 8;
                    float2 x = *(const float2*)(Xs + row * DD + col);
                    x.x += c[ni][h*2+0] + BO2s[col];
                    x.y += c[ni][h*2+1] + BO2s[col+1];
                    *(float2*)(Xs + row * DD + col) = x;
                }
        }
        __syncthreads();
    }

    // ---------- readout head (scratch in Ws region) ----------
    float* HD = Wsf;
    if (tid < DD) {
        float s = 0.f;
        #pragma unroll
        for (int i = 0; i < NA; i++) s += Xs[i * DD + tid];
        HD[tid] = s;
    }
    __syncthreads();
    if (tid < DD) {
        float acc = 0.f;
        #pragma unroll 8
        for (int k = 0; k < DD; k++) acc = fmaf(HD[k], Wh1[k * DD + tid], acc);
        float hpre = acc + bh1[tid];
        float h = hpre / (1.f + __expf(-hpre));
        HD[DD + tid] = h * Wh2[tid];
    }
    __syncthreads();
    if (tid == 0) {
        float s = bh2[0];
        #pragma unroll 8
        for (int k = 0; k < DD; k++) s += HD[DD + k];
        out[mol] = s;
    }
}

extern "C" void kernel_launch(void* const* d_in, const int* in_sizes, int n_in,
                              void* d_out, int out_size)
{
    const int*   Z   = (const int*)  d_in[0];
    const float* pos = (const float*)d_in[1];
    const float* emb = (const float*)d_in[6];
    const float* Wi  = (const float*)d_in[7];
    const float* Wf1 = (const float*)d_in[8];
    const float* bf1 = (const float*)d_in[9];
    const float* Wf2 = (const float*)d_in[10];
    const float* bf2 = (const float*)d_in[11];
    const float* Wo1 = (const float*)d_in[12];
    const float* bo1 = (const float*)d_in[13];
    const float* Wo2 = (const float*)d_in[14];
    const float* bo2 = (const float*)d_in[15];
    const float* Wh1 = (const float*)d_in[16];
    const float* bh1 = (const float*)d_in[17];
    const float* Wh2 = (const float*)d_in[18];
    const float* bh2 = (const float*)d_in[19];

    const int B = out_size;
    const int smemA = A_FLOATS * sizeof(float);
    cudaFuncSetAttribute(build_table,
                         cudaFuncAttributeMaxDynamicSharedMemorySize, smemA);
    cudaFuncSetAttribute(schnet_main,
                         cudaFuncAttributeMaxDynamicSharedMemorySize, SMEM_BYTES);

    build_table<<<dim3(TKNOTS / 128, NLAY), 256, smemA>>>(Wf1, bf1, Wf2, bf2);
    build_wsplit<<<(3 * NLAY * DD * (DD / 2) + 1023) / 1024, 1024>>>(Wi, Wo1, Wo2);
    schnet_main<<<B, NB, SMEM_BYTES>>>(Z, pos, emb, bo1, bo2,
                                       Wh1, bh1, Wh2, bh2, (float*)d_out);
}